// round 5
// baseline (speedup 1.0000x reference)
#include <cuda_runtime.h>
#include <cuda_bf16.h>
#include <math.h>

// x, x_r : (1, 3, 32, 512, 512) fp32. hc=wc=32, 16x16 patches/frame, T=32.
// |(x+1)/2-(xr+1)/2| = |x-xr|/2. Patch elems = 3*32*32 = 3072 (= 768 float4).
// Persistent ticket kernel: CTAs grab chunks of 8 patches; per patch the 256
// threads read 3 float4 each per tensor (thread -> fixed (row,col), i = channel).

#define T_FRAMES   32
#define NPATCHES   8192          // 32 frames * 256 patches
#define CHUNK      8
#define GRID       1184          // >= resident capacity; excess blocks no-op
#define CH_STRIDE  (32 * 512 * 512)   // channel stride in floats

__device__ int g_frame_max[T_FRAMES] = {0};  // float bits; >= 0 so int atomicMax OK
__device__ unsigned g_done = 0;
__device__ unsigned g_ticket = 0;

__global__ __launch_bounds__(256) void patch_kernel(const float* __restrict__ x,
                                                    const float* __restrict__ xr,
                                                    float* __restrict__ out) {
    __shared__ float warp_sums[8];
    __shared__ int   s_base;
    __shared__ int   s_last;

    const int tid  = threadIdx.x;
    const int lane = tid & 31;
    const int wid  = tid >> 5;
    // thread's fixed offset inside a patch: row = tid>>3 (0..31), col4 = tid&7
    const int thr_off = (tid >> 3) * 512 + (tid & 7) * 4;

    float s_prev = 0.0f;
    int   t_prev = -1;

    for (;;) {
        if (tid == 0) s_base = (int)atomicAdd(&g_ticket, (unsigned)CHUNK);
        __syncthreads();
        int base = s_base;
        __syncthreads();                      // protect s_base before next write
        if (base >= NPATCHES) break;
        int lim = min(base + CHUNK, NPATCHES);

        for (int pb = base; pb < lim; pb++) {
            int t  = pb >> 8;
            int p  = pb & 255;
            int o0 = t * (512 * 512) + (p >> 4) * (32 * 512) + (p & 15) * 32 + thr_off;

            // Issue all 12 loads for THIS patch first ...
            const float4* px = (const float4*)(x  + o0);
            const float4* pr = (const float4*)(xr + o0);
            float4 a0 = __ldcs(px);
            float4 a1 = __ldcs(px + CH_STRIDE / 4);
            float4 a2 = __ldcs(px + 2 * (CH_STRIDE / 4));
            float4 r0 = __ldcs(pr);
            float4 r1 = __ldcs(pr + CH_STRIDE / 4);
            float4 r2 = __ldcs(pr + 2 * (CH_STRIDE / 4));

            // ... then reduce the PREVIOUS patch while loads are in flight.
            if (t_prev >= 0) {
                float v = s_prev;
                #pragma unroll
                for (int o = 16; o > 0; o >>= 1)
                    v += __shfl_xor_sync(0xffffffffu, v, o);
                if (lane == 0) warp_sums[wid] = v;
                __syncthreads();
                if (wid == 0) {
                    float w = (lane < 8) ? warp_sums[lane] : 0.0f;
                    w += __shfl_xor_sync(0xffffffffu, w, 1);
                    w += __shfl_xor_sync(0xffffffffu, w, 2);
                    w += __shfl_xor_sync(0xffffffffu, w, 4);
                    if (lane == 0)
                        atomicMax(&g_frame_max[t_prev],
                                  __float_as_int(w * (1.0f / 6144.0f)));
                }
                __syncthreads();              // protect warp_sums reuse
            }

            s_prev = fabsf(a0.x - r0.x) + fabsf(a0.y - r0.y)
                   + fabsf(a0.z - r0.z) + fabsf(a0.w - r0.w)
                   + fabsf(a1.x - r1.x) + fabsf(a1.y - r1.y)
                   + fabsf(a1.z - r1.z) + fabsf(a1.w - r1.w)
                   + fabsf(a2.x - r2.x) + fabsf(a2.y - r2.y)
                   + fabsf(a2.z - r2.z) + fabsf(a2.w - r2.w);
            t_prev = t;
        }
    }

    // Flush the last pending patch of this block.
    if (t_prev >= 0) {
        float v = s_prev;
        #pragma unroll
        for (int o = 16; o > 0; o >>= 1)
            v += __shfl_xor_sync(0xffffffffu, v, o);
        if (lane == 0) warp_sums[wid] = v;
        __syncthreads();
        if (wid == 0) {
            float w = (lane < 8) ? warp_sums[lane] : 0.0f;
            w += __shfl_xor_sync(0xffffffffu, w, 1);
            w += __shfl_xor_sync(0xffffffffu, w, 2);
            w += __shfl_xor_sync(0xffffffffu, w, 4);
            if (lane == 0)
                atomicMax(&g_frame_max[t_prev],
                          __float_as_int(w * (1.0f / 6144.0f)));
        }
        __syncthreads();
    }

    // Completion: last block computes the final scalar and resets state.
    if (tid == 0) {
        __threadfence();
        unsigned prev = atomicAdd(&g_done, 1u);
        s_last = (prev == GRID - 1);
    }
    __syncthreads();
    if (s_last && wid == 0) {
        float fm = __int_as_float(g_frame_max[lane]);   // lane -> frame, >= 0
        float sum = fm;
        #pragma unroll
        for (int o = 16; o > 0; o >>= 1)
            sum += __shfl_xor_sync(0xffffffffu, sum, o);
        if (lane == 0) {
            out[0] = logf(sum * (1.0f / (float)T_FRAMES));
            g_done   = 0;                                // reset for next replay
            g_ticket = 0;
        }
        g_frame_max[lane] = 0;                           // reset (and clamp at 0)
    }
}

extern "C" void kernel_launch(void* const* d_in, const int* in_sizes, int n_in,
                              void* d_out, int out_size) {
    const float* x  = (const float*)d_in[0];
    const float* xr = (const float*)d_in[1];
    patch_kernel<<<GRID, 256>>>(x, xr, (float*)d_out);
}

// round 6
// speedup vs baseline: 1.0069x; 1.0069x over previous
#include <cuda_runtime.h>
#include <cuda_bf16.h>
#include <math.h>

// x, x_r : (1, 3, 32, 512, 512) fp32. hc=wc=32, 16x16 patches/frame, T=32.
// |(x+1)/2-(xr+1)/2| = |x-xr|/2. Patch elems = 3*32*32 = 3072 (= 768 float4).
//
// One WARP per patch: no __syncthreads in the hot path, no smem reduction.
// 2048 blocks x 128 threads = 8192 warps = 8192 patches.
// Lane -> (row-quad, col4): rows j*4 + (lane>>3), col4 = lane&7.
// 24 float4 per thread per tensor, accumulated over an unrolled loop.

#define T_FRAMES  32
#define NBLOCKS   2048
#define CH_STRIDE (32 * 512 * 512)   // channel stride (floats)

__device__ int g_frame_max[T_FRAMES] = {0};  // float bits; >= 0 so int atomicMax OK
__device__ unsigned g_done = 0;

__global__ __launch_bounds__(128) void patch_kernel(const float* __restrict__ x,
                                                    const float* __restrict__ xr,
                                                    float* __restrict__ out) {
    const int tid  = threadIdx.x;
    const int lane = tid & 31;
    const int wid  = tid >> 5;

    const int gw = blockIdx.x * 4 + wid;     // 0 .. 8191 : patch id
    const int t  = gw >> 8;                  // frame
    const int p  = gw & 255;
    const int h0 = (p >> 4) * 32;
    const int w0 = (p & 15) * 32;

    // base offset for channel 0, this thread's first element
    const int o0 = (t * 512 + h0 + (lane >> 3)) * 512 + w0 + ((lane & 7) << 2);

    float s0 = 0.0f, s1 = 0.0f;
    #pragma unroll
    for (int c = 0; c < 3; c++) {
        const float4* px = (const float4*)(x  + o0 + c * CH_STRIDE);
        const float4* pr = (const float4*)(xr + o0 + c * CH_STRIDE);
        // 8 row-quads of 4 rows each; stride per quad = 4*512 floats = 512 float4
        #pragma unroll
        for (int j = 0; j < 8; j += 2) {
            float4 a0 = __ldcs(px + (j    ) * 512);
            float4 r0 = __ldcs(pr + (j    ) * 512);
            float4 a1 = __ldcs(px + (j + 1) * 512);
            float4 r1 = __ldcs(pr + (j + 1) * 512);
            s0 += fabsf(a0.x - r0.x) + fabsf(a0.y - r0.y)
                + fabsf(a0.z - r0.z) + fabsf(a0.w - r0.w);
            s1 += fabsf(a1.x - r1.x) + fabsf(a1.y - r1.y)
                + fabsf(a1.z - r1.z) + fabsf(a1.w - r1.w);
        }
    }
    float s = s0 + s1;

    // warp reduce (no barriers anywhere above)
    #pragma unroll
    for (int o = 16; o > 0; o >>= 1)
        s += __shfl_xor_sync(0xffffffffu, s, o);

    if (lane == 0)
        atomicMax(&g_frame_max[t], __float_as_int(s * (1.0f / 6144.0f)));  // >= 0

    // Completion: last block computes the final scalar and resets state.
    __shared__ int s_last;
    __syncthreads();
    if (tid == 0) {
        __threadfence();
        unsigned prev = atomicAdd(&g_done, 1u);
        s_last = (prev == NBLOCKS - 1);
    }
    __syncthreads();
    if (s_last && wid == 0) {
        float fm = __int_as_float(g_frame_max[lane]);   // lane -> frame, >= 0
        float sum = fm;
        #pragma unroll
        for (int o = 16; o > 0; o >>= 1)
            sum += __shfl_xor_sync(0xffffffffu, sum, o);
        if (lane == 0) {
            out[0] = logf(sum * (1.0f / (float)T_FRAMES));
            g_done = 0;                                  // reset for next replay
        }
        g_frame_max[lane] = 0;                           // reset (and clamp at 0)
    }
}

extern "C" void kernel_launch(void* const* d_in, const int* in_sizes, int n_in,
                              void* d_out, int out_size) {
    const float* x  = (const float*)d_in[0];
    const float* xr = (const float*)d_in[1];
    patch_kernel<<<NBLOCKS, 128>>>(x, xr, (float*)d_out);
}

// round 7
// speedup vs baseline: 1.0316x; 1.0245x over previous
#include <cuda_runtime.h>
#include <cuda_bf16.h>
#include <math.h>
#include <stdint.h>

// x, x_r : (1, 3, 32, 512, 512) fp32. hc=wc=32, 16x16 patches/frame, T=32.
// |(x+1)/2-(xr+1)/2| = |x-xr|/2. Patch elems = 3*32*32 = 3072.
//
// TMA (cp.async.bulk) pipeline: 256 CTAs x 256 thr, each CTA = 2 strips
// (t, ph). Strip = 32 rows x 512 cols x 3 ch. 12 chunks/strip, chunk =
// (16KB x + 16KB xr) = one (channel, 8-row block). 3-stage smem ring,
// producer thread 0 with lookahead 2, full/empty mbarriers.

#define T_FRAMES   32
#define CH_STRIDE  (32 * 512 * 512)   // floats
#define GRID       256
#define NSTAGES    3
#define HALF       16384              // bytes per tensor per chunk
#define STAGE_B    (2 * HALF)         // 32KB per stage
#define NITER      24                 // 2 strips * 12 chunks

__device__ int g_frame_max[T_FRAMES] = {0};  // float bits; >= 0 so atomicMax(int) OK
__device__ unsigned g_done = 0;

static __device__ __forceinline__ uint32_t smem_u32(const void* p) {
    uint32_t a;
    asm("{ .reg .u64 t; cvta.to.shared.u64 t, %1; cvt.u32.u64 %0, t; }"
        : "=r"(a) : "l"(p));
    return a;
}
static __device__ __forceinline__ void mbar_init(uint32_t a, uint32_t cnt) {
    asm volatile("mbarrier.init.shared.b64 [%0], %1;" :: "r"(a), "r"(cnt) : "memory");
}
static __device__ __forceinline__ void mbar_expect_tx(uint32_t a, uint32_t bytes) {
    asm volatile("mbarrier.arrive.expect_tx.shared::cta.b64 _, [%0], %1;"
                 :: "r"(a), "r"(bytes) : "memory");
}
static __device__ __forceinline__ void mbar_arrive(uint32_t a) {
    asm volatile("mbarrier.arrive.shared::cta.b64 _, [%0];" :: "r"(a) : "memory");
}
static __device__ __forceinline__ void mbar_wait(uint32_t a, uint32_t parity) {
    asm volatile(
        "{\n\t.reg .pred P;\n"
        "LW_%=:\n\t"
        "mbarrier.try_wait.parity.shared::cta.b64 P, [%0], %1;\n\t"
        "@P bra LD_%=;\n\t"
        "bra LW_%=;\n"
        "LD_%=:\n\t}"
        :: "r"(a), "r"(parity) : "memory");
}
static __device__ __forceinline__ void bulk_g2s(uint32_t dst, const void* src,
                                                uint32_t bytes, uint32_t mbar) {
    asm volatile(
        "cp.async.bulk.shared::cluster.global.mbarrier::complete_tx::bytes "
        "[%0], [%1], %2, [%3];"
        :: "r"(dst), "l"(src), "r"(bytes), "r"(mbar) : "memory");
}

__global__ __launch_bounds__(256) void patch_kernel(const float* __restrict__ x,
                                                    const float* __restrict__ xr,
                                                    float* __restrict__ out) {
    extern __shared__ __align__(128) char dsm[];
    __shared__ uint64_t mb_full[NSTAGES];
    __shared__ uint64_t mb_empty[NSTAGES];
    __shared__ float psum[16];
    __shared__ int s_last;

    const int tid  = threadIdx.x;
    const int lane = tid & 31;
    const int wid  = tid >> 5;
    const int col4 = tid & 127;        // float4 column 0..127 within a 512-row
    const int rgrp = tid >> 7;         // 0/1: base row within 8-row chunk
    const int pw   = col4 >> 3;        // fixed patch column for this thread

    const uint32_t full_a  = smem_u32(mb_full);
    const uint32_t empty_a = smem_u32(mb_empty);
    const uint32_t dsm_a   = smem_u32(dsm);

    if (tid == 0) {
        #pragma unroll
        for (int s = 0; s < NSTAGES; s++) {
            mbar_init(full_a  + 8u * s, 1);   // expect_tx arrive
            mbar_init(empty_a + 8u * s, 8);   // one arrive per warp
        }
    }
    __syncthreads();

    const int strip0 = blockIdx.x * 2;

    // --- producer: issue chunk k into stage k%3 ---
    auto issue = [&](int k) {
        int strip = strip0 + (k >= 12);
        int t  = strip >> 4;
        int ph = strip & 15;
        int m  = (k >= 12) ? k - 12 : k;
        int c  = m >> 2;                 // channel
        int rb = m & 3;                  // 8-row block
        size_t goff = (size_t)c * CH_STRIDE
                    + (size_t)((t * 512 + ph * 32 + rb * 8)) * 512;
        int st = k % NSTAGES;
        uint32_t d  = dsm_a + (uint32_t)st * STAGE_B;
        uint32_t fb = full_a + 8u * st;
        mbar_expect_tx(fb, STAGE_B);
        bulk_g2s(d,        x  + goff, HALF, fb);
        bulk_g2s(d + HALF, xr + goff, HALF, fb);
    };

    // prologue: fill 2 stages (fresh barriers: no empty wait needed)
    if (tid == 0) { issue(0); issue(1); }

    float s_acc = 0.0f;

    for (int k = 0; k < NITER; k++) {
        // producer lookahead
        if (tid == 0 && k + 2 < NITER) {
            int kk = k + 2;
            if (kk >= NSTAGES)
                mbar_wait(empty_a + 8u * (kk % NSTAGES), ((kk / NSTAGES) & 1u) ^ 1u);
            issue(kk);
        }

        // consume stage k
        int st = k % NSTAGES;
        mbar_wait(full_a + 8u * st, (k / NSTAGES) & 1u);

        const char* base = dsm + st * STAGE_B;
        #pragma unroll
        for (int r = 0; r < 4; r++) {
            int off = (rgrp + 2 * r) * 2048 + col4 * 16;   // bytes within 16KB chunk
            float4 a  = *(const float4*)(base + off);
            float4 rr = *(const float4*)(base + HALF + off);
            s_acc += fabsf(a.x - rr.x) + fabsf(a.y - rr.y)
                   + fabsf(a.z - rr.z) + fabsf(a.w - rr.w);
        }
        __syncwarp();
        if (lane == 0) mbar_arrive(empty_a + 8u * st);

        // end of a strip: reduce 16 patch sums, frame-max atomic
        if ((k == 11) || (k == 23)) {
            int strip = strip0 + (k >= 12);
            int t = strip >> 4;
            if (tid < 16) psum[tid] = 0.0f;
            __syncthreads();
            float v = s_acc;
            v += __shfl_xor_sync(0xffffffffu, v, 1);
            v += __shfl_xor_sync(0xffffffffu, v, 2);
            v += __shfl_xor_sync(0xffffffffu, v, 4);
            if ((lane & 7) == 0) atomicAdd(&psum[pw], v);
            __syncthreads();
            if (wid == 0) {
                float pm = (lane < 16) ? psum[lane] * (1.0f / 6144.0f) : 0.0f;
                #pragma unroll
                for (int o = 8; o > 0; o >>= 1)
                    pm = fmaxf(pm, __shfl_xor_sync(0xffffffffu, pm, o));
                if (lane == 0)
                    atomicMax(&g_frame_max[t], __float_as_int(pm));  // pm >= 0
            }
            s_acc = 0.0f;
        }
    }

    // completion: last CTA computes final scalar, resets state for replay
    __syncthreads();
    if (tid == 0) {
        __threadfence();
        unsigned prev = atomicAdd(&g_done, 1u);
        s_last = (prev == GRID - 1);
    }
    __syncthreads();
    if (s_last && wid == 0) {
        float fm = __int_as_float(g_frame_max[lane]);   // lane -> frame, >= 0
        float sum = fm;
        #pragma unroll
        for (int o = 16; o > 0; o >>= 1)
            sum += __shfl_xor_sync(0xffffffffu, sum, o);
        if (lane == 0) {
            out[0] = logf(sum * (1.0f / (float)T_FRAMES));
            g_done = 0;
        }
        g_frame_max[lane] = 0;                           // reset (and clamp at 0)
    }
}

extern "C" void kernel_launch(void* const* d_in, const int* in_sizes, int n_in,
                              void* d_out, int out_size) {
    const float* x  = (const float*)d_in[0];
    const float* xr = (const float*)d_in[1];
    cudaFuncSetAttribute(patch_kernel, cudaFuncAttributeMaxDynamicSharedMemorySize,
                         NSTAGES * STAGE_B);
    patch_kernel<<<GRID, 256, NSTAGES * STAGE_B>>>(x, xr, (float*)d_out);
}

// round 12
// speedup vs baseline: 1.2538x; 1.2154x over previous
#include <cuda_runtime.h>
#include <cuda_bf16.h>
#include <math.h>

// x, x_r : (1, 3, 32, 512, 512) fp32. hc=wc=32, 16x16 patches/frame, T=32.
// |(x+1)/2-(xr+1)/2| = |x-xr|/2. Patch elems = 3*32*32 = 3072 (= 768 float4).
// One block per patch (8192 x 256): measured-best decomposition; ~99% of the
// device's dual-stream read roofline (~5.83 TB/s).

#define T_FRAMES 32
#define H_DIM    512
#define W_DIM    512
#define NBLOCKS  (T_FRAMES * 256)       // 8192
#define CH_STRIDE (T_FRAMES * H_DIM * W_DIM)   // 8388608 floats

__device__ int g_frame_max[T_FRAMES] = {0};  // float bits; >= 0 so int atomicMax OK
__device__ unsigned g_done = 0;

__global__ __launch_bounds__(256) void patch_kernel(const float* __restrict__ x,
                                                    const float* __restrict__ xr,
                                                    float* __restrict__ out) {
    const int b  = blockIdx.x;               // 0 .. 8191
    const int t  = b >> 8;                   // frame
    const int p  = b & 255;                  // patch within frame
    const int tid = threadIdx.x;

    // thread's fixed (row, col4) inside the patch: row = tid>>3, col4 = tid&7
    // base offset (channel 0): fits in int32 (max < 2^25)
    const int o0 = (t * H_DIM + (p >> 4) * 32 + (tid >> 3)) * W_DIM
                 + (p & 15) * 32 + ((tid & 7) << 2);

    const float4* px = (const float4*)(x  + o0);
    const float4* pr = (const float4*)(xr + o0);

    // Front-batch all 6 independent LDG.128 (channels 0..2, both tensors)
    float4 a0 = px[0];
    float4 a1 = px[CH_STRIDE / 4];
    float4 a2 = px[2 * (CH_STRIDE / 4)];
    float4 r0 = pr[0];
    float4 r1 = pr[CH_STRIDE / 4];
    float4 r2 = pr[2 * (CH_STRIDE / 4)];

    float s = fabsf(a0.x - r0.x) + fabsf(a0.y - r0.y)
            + fabsf(a0.z - r0.z) + fabsf(a0.w - r0.w)
            + fabsf(a1.x - r1.x) + fabsf(a1.y - r1.y)
            + fabsf(a1.z - r1.z) + fabsf(a1.w - r1.w)
            + fabsf(a2.x - r2.x) + fabsf(a2.y - r2.y)
            + fabsf(a2.z - r2.z) + fabsf(a2.w - r2.w);

    // warp reduce
    #pragma unroll
    for (int o = 16; o > 0; o >>= 1)
        s += __shfl_xor_sync(0xffffffffu, s, o);

    __shared__ float warp_sums[8];
    const int lane = tid & 31, wid = tid >> 5;
    if (lane == 0) warp_sums[wid] = s;
    __syncthreads();

    if (wid == 0) {
        float v = (lane < 8) ? warp_sums[lane] : 0.0f;
        v += __shfl_xor_sync(0xffffffffu, v, 1);
        v += __shfl_xor_sync(0xffffffffu, v, 2);
        v += __shfl_xor_sync(0xffffffffu, v, 4);

        bool last = false;
        if (lane == 0) {
            float pm = v * (1.0f / 6144.0f);             // /3072 (mean) and /2
            atomicMax(&g_frame_max[t], __float_as_int(pm));
            __threadfence();
            unsigned prev = atomicAdd(&g_done, 1u);
            last = (prev == NBLOCKS - 1);
        }
        last = __shfl_sync(0xffffffffu, (int)last, 0);

        if (last) {
            float fm = __int_as_float(g_frame_max[lane]);   // lane -> frame, >= 0
            float sum = fm;
            #pragma unroll
            for (int o = 16; o > 0; o >>= 1)
                sum += __shfl_xor_sync(0xffffffffu, sum, o);
            if (lane == 0) {
                out[0] = logf(sum * (1.0f / (float)T_FRAMES));
                g_done = 0;                                 // reset for next replay
            }
            g_frame_max[lane] = 0;                          // reset (and clamp at 0)
        }
    }
}

extern "C" void kernel_launch(void* const* d_in, const int* in_sizes, int n_in,
                              void* d_out, int out_size) {
    const float* x  = (const float*)d_in[0];
    const float* xr = (const float*)d_in[1];
    patch_kernel<<<NBLOCKS, 256>>>(x, xr, (float*)d_out);
}